// round 1
// baseline (speedup 1.0000x reference)
#include <cuda_runtime.h>
#include <cuda_bf16.h>

#define TILE  128
#define HALO  12
#define KWIN  9
#define DIL   3
#define HD    32
#define KV_W  (TILE + 2*HALO)   /* 152 */
#define ROW   36                /* padded row stride (floats): conflict-free LDS.128 */

__global__ __launch_bounds__(TILE, 1)
void dilated_attn_kernel(const float* __restrict__ q,
                         const float* __restrict__ k,
                         const float* __restrict__ v,
                         float* __restrict__ out,
                         int B, int d, int L)
{
    __shared__ float ks[KV_W][ROW];
    __shared__ float vs[KV_W][ROW];

    const int t    = threadIdx.x;
    const int tile = blockIdx.x & 31;          // L/TILE = 32 tiles
    const int h    = (blockIdx.x >> 5) & 15;   // 16 heads
    const int b    = blockIdx.x >> 9;          // 4 batches
    const int n0   = tile * TILE;

    const long chan_base = ((long)b * d + h * HD) * L;

    // Stage k/v tile (with halo) into shared, transposed to [token][dim].
    // Out-of-range sequence positions are zero-filled, which exactly matches
    // the reference's Unfold zero-padding semantics (score = 0, v contrib = 0).
    for (int idx = t; idx < HD * KV_W; idx += TILE) {
        const int c  = idx / KV_W;
        const int nl = idx - c * KV_W;
        const int n  = n0 - HALO + nl;
        float kvv = 0.f, vvv = 0.f;
        if ((unsigned)n < (unsigned)L) {
            const long g = chan_base + (long)c * L + n;
            kvv = k[g];
            vvv = v[g];
        }
        ks[nl][c] = kvv;
        vs[nl][c] = vvv;
    }
    __syncthreads();

    const int n = n0 + t;

    // q for this token into registers (coalesced per-dim across the warp)
    float4 qr[HD / 4];
    #pragma unroll
    for (int c4 = 0; c4 < HD / 4; c4++) {
        float4 qv;
        qv.x = q[chan_base + (long)(c4 * 4 + 0) * L + n];
        qv.y = q[chan_base + (long)(c4 * 4 + 1) * L + n];
        qv.z = q[chan_base + (long)(c4 * 4 + 2) * L + n];
        qv.w = q[chan_base + (long)(c4 * 4 + 3) * L + n];
        qr[c4] = qv;
    }

    // QK^T over the 9-wide dilated window
    float acc[KWIN];
    #pragma unroll
    for (int kk = 0; kk < KWIN; kk++) acc[kk] = 0.f;

    #pragma unroll
    for (int c4 = 0; c4 < HD / 4; c4++) {
        const float4 qv = qr[c4];
        #pragma unroll
        for (int kk = 0; kk < KWIN; kk++) {
            const float4 kv = *(const float4*)&ks[t + DIL * kk][c4 * 4];
            acc[kk] += qv.x * kv.x + qv.y * kv.y + qv.z * kv.z + qv.w * kv.w;
        }
    }

    // softmax over 9 (scaled by hd^-0.5)
    const float scale = 0.17677669529663687f;  // 32^-0.5
    float mx = -1e30f;
    #pragma unroll
    for (int kk = 0; kk < KWIN; kk++) { acc[kk] *= scale; mx = fmaxf(mx, acc[kk]); }
    float sum = 0.f;
    #pragma unroll
    for (int kk = 0; kk < KWIN; kk++) { acc[kk] = __expf(acc[kk] - mx); sum += acc[kk]; }
    const float inv = 1.f / sum;

    // attn @ V
    float4 o[HD / 4];
    #pragma unroll
    for (int c4 = 0; c4 < HD / 4; c4++) o[c4] = make_float4(0.f, 0.f, 0.f, 0.f);

    #pragma unroll
    for (int kk = 0; kk < KWIN; kk++) {
        const float w = acc[kk] * inv;
        #pragma unroll
        for (int c4 = 0; c4 < HD / 4; c4++) {
            const float4 vv = *(const float4*)&vs[t + DIL * kk][c4 * 4];
            o[c4].x += w * vv.x;
            o[c4].y += w * vv.y;
            o[c4].z += w * vv.z;
            o[c4].w += w * vv.w;
        }
    }

    // out[b][0][n][h*32 + c] : 32 contiguous floats per thread -> 8x STG.128
    float4* op = (float4*)(out + ((long)b * L + n) * d + h * HD);
    #pragma unroll
    for (int c4 = 0; c4 < HD / 4; c4++) op[c4] = o[c4];
}

extern "C" void kernel_launch(void* const* d_in, const int* in_sizes, int n_in,
                              void* d_out, int out_size)
{
    const float* q = (const float*)d_in[0];
    const float* k = (const float*)d_in[1];
    const float* v = (const float*)d_in[2];
    float* out = (float*)d_out;

    const int B = 4, d = 512, L = 4096;
    const int grid = B * (d / HD) * (L / TILE);   // 4 * 16 * 32 = 2048
    dilated_attn_kernel<<<grid, TILE>>>(q, k, v, out, B, d, L);
}